// round 3
// baseline (speedup 1.0000x reference)
#include <cuda_runtime.h>
#include <math.h>

#define N0 2048
#define NPAD 4096
#define NTHREADS 256
#define NBLOCKS 296         // 2 blocks/SM on 148 SMs (GB300 has 152 -> still co-resident)
#define NPHASES 100         // 50 iterations x 2 half-steps

#define EPS 0.05f
// log2(e)/EPS
#define KCONST 28.853900817779268f
// EPS * (-log(4096))
#define ACONST -0.41588830833596715f
// EPS * ln(2)
#define ELN2 0.034657359027997264f
#define SCALE 4096.0f

// ---- device state (no allocations allowed; static globals) ----
__device__ float g_u[N0];
__device__ float g_v[N0];
__device__ float g_upad;
__device__ float g_vpad;
__device__ unsigned int g_ctr;
__device__ float g_CT[(size_t)N0 * N0];   // C transposed (16 MB scratch)

__device__ __forceinline__ float ex2(float x) {
    float y;
    asm("ex2.approx.ftz.f32 %0, %1;" : "=f"(y) : "f"(x));
    return y;
}
__device__ __forceinline__ float lg2(float x) {
    float y;
    asm("lg2.approx.ftz.f32 %0, %1;" : "=f"(y) : "f"(x));
    return y;
}

__device__ __forceinline__ float warpRedSum(float v) {
#pragma unroll
    for (int o = 16; o > 0; o >>= 1) v += __shfl_down_sync(0xffffffffu, v, o);
    return v;
}

// ---- transpose C -> g_CT (so the column pass reads coalesced rows) ----
__global__ void transpose_kernel(const float* __restrict__ in) {
    __shared__ float tile[32][33];
    int x = blockIdx.x * 32 + threadIdx.x;
    int y0 = blockIdx.y * 32 + threadIdx.y;
#pragma unroll
    for (int k = 0; k < 32; k += 8)
        tile[threadIdx.y + k][threadIdx.x] = in[(size_t)(y0 + k) * N0 + x];
    __syncthreads();
    int x2 = blockIdx.y * 32 + threadIdx.x;
    int y2 = blockIdx.x * 32 + threadIdx.y;
#pragma unroll
    for (int k = 0; k < 32; k += 8)
        g_CT[(size_t)(y2 + k) * N0 + x2] = tile[threadIdx.x][threadIdx.y + k];
}

// ---- initial state: v = 0, v_pad = 0, barrier counter = 0 (replay-safe) ----
__global__ void init_kernel() {
    for (int j = threadIdx.x; j < N0; j += blockDim.x) g_v[j] = 0.0f;
    if (threadIdx.x == 0) {
        g_vpad = 0.0f;
        g_ctr = 0u;
    }
}

// Persistent kernel: all 100 Sinkhorn half-steps in one launch, separated by a
// grid-wide fence+atomic barrier. All 296 blocks are co-resident
// (__launch_bounds__(256,2) => <=128 regs => 2 blocks/SM), so the barrier
// cannot deadlock.
//
// No max-shift needed: C in [0,1], eps=0.05 keeps potentials in ~[-1, 0.5],
// so exp2 args stay well inside fp32 range.
//
// phase even (row):  reads v/v_pad + C rows   -> writes u/u_pad
// phase odd  (col):  reads u/u_pad + CT rows  -> writes v/v_pad
//
// x_out[r] = ACONST - eps*ln( sum_j exp2(K*(x_in[j] - M[r][j])) + P ),
//   P = 2048 * exp2(K*x_pad_in)   (contribution of the 2048 zero pad cols/rows)
//
// Coherency: u/v/pads are produced by other SMs between phases, so ALL
// accesses to them use .cg (L2) — never L1. C/CT rows are immutable: __ldg,
// and each SM's ~14 rows (~224KB) stay hot in L1 across all phases.
__global__ void __launch_bounds__(NTHREADS, 2) sinkhorn_persistent(const float* __restrict__ C) {
    const int tid = threadIdx.x;
    const int warp = tid >> 5, lane = tid & 31;
    const int b = blockIdx.x;

    const int start = (N0 * b) / NBLOCKS;
    const int cnt = (N0 * (b + 1)) / NBLOCKS - start;   // 6 or 7
    const int row = start + warp;
    const bool doRow = (warp < cnt);
    const bool doPad = (b == 0 && warp == 7);           // warp 7 never owns a row

    unsigned int target = 0;

    for (int ph = 0; ph < NPHASES; ++ph) {
        const int odd = ph & 1;
        const float* __restrict__ M = odd ? g_CT : C;
        const float* xin = odd ? g_u : g_v;
        float* xout = odd ? g_v : g_u;

        const float xpad_in = __ldcg(odd ? &g_upad : &g_vpad);
        const float P = 2048.0f * ex2(KCONST * xpad_in);
        const float4* x4 = (const float4*)xin;

        if (doRow) {
            const float4* r4 = (const float4*)(M + (size_t)row * N0);
            float s = 0.0f;
#pragma unroll
            for (int k = 0; k < 16; ++k) {
                const int idx = lane + k * 32;
                float4 c = __ldg(r4 + idx);
                float4 x = __ldcg(x4 + idx);
                s += ex2(fmaf(-KCONST, c.x, KCONST * x.x));
                s += ex2(fmaf(-KCONST, c.y, KCONST * x.y));
                s += ex2(fmaf(-KCONST, c.z, KCONST * x.z));
                s += ex2(fmaf(-KCONST, c.w, KCONST * x.w));
            }
            s = warpRedSum(s);
            if (lane == 0) __stcg(&xout[row], ACONST - ELN2 * lg2(s + P));
        } else if (doPad) {
            // pad potential: same update with a zero matrix row
            float s = 0.0f;
#pragma unroll
            for (int k = 0; k < 16; ++k) {
                float4 x = __ldcg(x4 + lane + k * 32);
                s += ex2(KCONST * x.x) + ex2(KCONST * x.y) +
                     ex2(KCONST * x.z) + ex2(KCONST * x.w);
            }
            s = warpRedSum(s);
            if (lane == 0) __stcg(odd ? &g_vpad : &g_upad, ACONST - ELN2 * lg2(s + P));
        }

        // ---- grid-wide barrier ----
        target += NBLOCKS;
        __syncthreads();
        if (tid == 0) {
            __threadfence();                       // publish xout/pad writes
            atomicAdd(&g_ctr, 1u);
            volatile unsigned int* p = &g_ctr;     // ld.volatile bypasses L1
            while (*p < target) {}
        }
        __syncthreads();
        __threadfence();                           // order before next phase's reads
    }
}

// ---- emit 4096 * exp(min(log_pi, 0)) over the padded 4096x4096 ----
__global__ void __launch_bounds__(NTHREADS) final_kernel(const float* __restrict__ C,
                                                         float* __restrict__ out) {
    int i = blockIdx.y;                                  // 0..4095
    int j4 = blockIdx.x * blockDim.x + threadIdx.x;      // float4 index 0..1023

    float u = (i < N0) ? g_u[i] : g_upad;

    float4 v4, c4;
    if (j4 < N0 / 4) {
        v4 = ((const float4*)g_v)[j4];
        if (i < N0)
            c4 = ((const float4*)C)[(size_t)i * (N0 / 4) + j4];
        else
            c4 = make_float4(0.f, 0.f, 0.f, 0.f);
    } else {
        float vp = g_vpad;
        v4 = make_float4(vp, vp, vp, vp);
        c4 = make_float4(0.f, 0.f, 0.f, 0.f);
    }

    float4 o;
    o.x = SCALE * ex2(fminf((u + v4.x - c4.x) * KCONST, 0.0f));
    o.y = SCALE * ex2(fminf((u + v4.y - c4.y) * KCONST, 0.0f));
    o.z = SCALE * ex2(fminf((u + v4.z - c4.z) * KCONST, 0.0f));
    o.w = SCALE * ex2(fminf((u + v4.w - c4.w) * KCONST, 0.0f));

    ((float4*)out)[(size_t)i * (NPAD / 4) + j4] = o;
}

extern "C" void kernel_launch(void* const* d_in, const int* in_sizes, int n_in,
                              void* d_out, int out_size) {
    const float* C = (const float*)d_in[0];
    float* out = (float*)d_out;

    transpose_kernel<<<dim3(N0 / 32, N0 / 32), dim3(32, 8)>>>(C);
    init_kernel<<<1, NTHREADS>>>();
    sinkhorn_persistent<<<NBLOCKS, NTHREADS>>>(C);
    final_kernel<<<dim3(NPAD / 4 / NTHREADS, NPAD), NTHREADS>>>(C, out);
}

// round 4
// speedup vs baseline: 1.6001x; 1.6001x over previous
#include <cuda_runtime.h>
#include <math.h>

#define N0 2048
#define NPAD 4096
#define NBLOCKS 148         // 1 block/SM, all co-resident
#define NT 512              // 16 warps/block; max 14 row-warps used
#define NPHASES 100         // 50 iterations x 2 half-steps

// log2(e)/EPS  (EPS = 0.05)
#define KCONST 28.853900817779268f
// 1/4096 = exp(ACONST/EPS)
#define AMASS 0.000244140625f
#define SCALE 4096.0f

// ---- device state (allocations forbidden; static globals) ----
__device__ float g_y[N0];          // e^{u/eps}
__device__ float g_z[N0];          // e^{v/eps}
__device__ float g_ypad, g_zpad;
__device__ __align__(128) unsigned int g_ctr;    // arrival counter
__device__ __align__(128) unsigned int g_flag;   // release flag (separate line)
__device__ float g_E [(size_t)N0 * N0];   // exp2(-K*C)          (16 MB)
__device__ float g_Et[(size_t)N0 * N0];   // transpose of g_E    (16 MB)

__device__ __forceinline__ float ex2(float x) {
    float y; asm("ex2.approx.ftz.f32 %0, %1;" : "=f"(y) : "f"(x)); return y;
}
__device__ __forceinline__ float rcp(float x) {
    float y; asm("rcp.approx.ftz.f32 %0, %1;" : "=f"(y) : "f"(x)); return y;
}
__device__ __forceinline__ float warpRedSum(float v) {
#pragma unroll
    for (int o = 16; o > 0; o >>= 1) v += __shfl_down_sync(0xffffffffu, v, o);
    return v;
}

// ---- fused: E = exp2(-K*C), Et = E^T ----
__global__ void prep_kernel(const float* __restrict__ in) {
    __shared__ float tile[32][33];
    int x = blockIdx.x * 32 + threadIdx.x;
    int y0 = blockIdx.y * 32 + threadIdx.y;
#pragma unroll
    for (int k = 0; k < 32; k += 8) {
        float c = in[(size_t)(y0 + k) * N0 + x];
        float e = ex2(-KCONST * c);
        g_E[(size_t)(y0 + k) * N0 + x] = e;
        tile[threadIdx.y + k][threadIdx.x] = e;
    }
    __syncthreads();
    int x2 = blockIdx.y * 32 + threadIdx.x;
    int y2 = blockIdx.x * 32 + threadIdx.y;
#pragma unroll
    for (int k = 0; k < 32; k += 8)
        g_Et[(size_t)(y2 + k) * N0 + x2] = tile[threadIdx.x][threadIdx.y + k];
}

// ---- initial state: v = 0 -> z = 1, z_pad = 1; barrier state reset (replay-safe) ----
__global__ void init_kernel() {
    for (int j = threadIdx.x; j < N0; j += blockDim.x) g_z[j] = 1.0f;
    if (threadIdx.x == 0) {
        g_zpad = 1.0f;
        g_ctr = 0u;
        g_flag = 0u;
    }
}

// Persistent kernel, primal (mass) domain — no transcendentals in the loop.
//
// phase even (row):  y_i = AMASS * rcp( sum_j E_ij  * z_j + 2048*z_pad )
// phase odd  (col):  z_j = AMASS * rcp( sum_i Et_ji * y_i + 2048*y_pad )
// pad:               x_pad = AMASS * rcp( sum_j in_j + 2048*in_pad )
//
// Exponents bounded (C in [0,1], eps=0.05 -> potentials in ~[-1,0.5]), so all
// masses stay well inside fp32 range.
//
// Each SM's 13-14 E rows + 13-14 Et rows (~224 KB) stay hot in its L1 across
// all 100 phases (no per-launch L1 flush inside one kernel). The input mass
// vector is staged into smem once per block per phase. y/z/pads cross SMs:
// .cg accesses only.
__global__ void __launch_bounds__(NT, 1) sinkhorn_persistent() {
    const int tid = threadIdx.x;
    const int warp = tid >> 5, lane = tid & 31;
    const int b = blockIdx.x;

    const int start = (N0 * b) / NBLOCKS;
    const int cnt = (N0 * (b + 1)) / NBLOCKS - start;   // 13 or 14
    const int row = start + warp;
    const bool doRow = (warp < cnt);
    const bool doPad = (b == 0 && warp == 15);          // warp 15 never owns a row

    __shared__ float zs[N0];
    unsigned int phnum = 0;

    for (int ph = 0; ph < NPHASES; ++ph) {
        const int odd = ph & 1;
        const float* __restrict__ M = odd ? g_Et : g_E;
        const float* xin = odd ? g_y : g_z;
        float* xout = odd ? g_z : g_y;

        const float xpad_in = __ldcg(odd ? &g_ypad : &g_zpad);
        const float padterm = 2048.0f * xpad_in;

        // stage input masses into smem (512 threads x float4 = 2048 floats)
        ((float4*)zs)[tid] = __ldcg(((const float4*)xin) + tid);
        __syncthreads();

        const float4* z4 = (const float4*)zs;
        if (doRow) {
            const float4* r4 = (const float4*)(M + (size_t)row * N0);
            float s = 0.0f;
#pragma unroll
            for (int k = 0; k < 16; ++k) {
                const int idx = lane + k * 32;
                float4 e = __ldg(r4 + idx);
                float4 z = z4[idx];
                s = fmaf(e.x, z.x, s);
                s = fmaf(e.y, z.y, s);
                s = fmaf(e.z, z.z, s);
                s = fmaf(e.w, z.w, s);
            }
            s = warpRedSum(s);
            if (lane == 0) __stcg(&xout[row], AMASS * rcp(s + padterm));
        } else if (doPad) {
            float s = 0.0f;
#pragma unroll
            for (int k = 0; k < 16; ++k) {
                float4 z = z4[lane + k * 32];
                s += (z.x + z.y) + (z.z + z.w);
            }
            s = warpRedSum(s);
            if (lane == 0) __stcg(odd ? &g_zpad : &g_ypad, AMASS * rcp(s + padterm));
        }

        // ---- grid barrier: counter + separate release flag, nanosleep backoff ----
        ++phnum;
        __syncthreads();                       // all warps done reading zs
        if (tid == 0) {
            __threadfence();                   // publish xout/pad writes
            unsigned int t = atomicAdd(&g_ctr, 1u) + 1u;
            if (t == NBLOCKS * phnum) {
                atomicExch(&g_flag, phnum);    // release
            } else {
                volatile unsigned int* f = &g_flag;
                while (*f < phnum) __nanosleep(32);
            }
            __threadfence();                   // acquire before next phase reads
        }
        __syncthreads();
    }
}

// ---- out = 4096 * min(1, y_i * z_j * E_ij) over padded 4096x4096 ----
__global__ void __launch_bounds__(256) final_kernel(float* __restrict__ out) {
    int i = blockIdx.y;                                  // 0..4095
    int j4 = blockIdx.x * blockDim.x + threadIdx.x;      // float4 index 0..1023

    float y = (i < N0) ? g_y[i] : g_ypad;

    float4 z4, e4;
    if (j4 < N0 / 4) {
        z4 = ((const float4*)g_z)[j4];
        if (i < N0)
            e4 = ((const float4*)g_E)[(size_t)i * (N0 / 4) + j4];
        else
            e4 = make_float4(1.f, 1.f, 1.f, 1.f);
    } else {
        float zp = g_zpad;
        z4 = make_float4(zp, zp, zp, zp);
        e4 = make_float4(1.f, 1.f, 1.f, 1.f);
    }

    float4 o;
    o.x = SCALE * fminf(1.0f, y * z4.x * e4.x);
    o.y = SCALE * fminf(1.0f, y * z4.y * e4.y);
    o.z = SCALE * fminf(1.0f, y * z4.z * e4.z);
    o.w = SCALE * fminf(1.0f, y * z4.w * e4.w);

    ((float4*)out)[(size_t)i * (NPAD / 4) + j4] = o;
}

extern "C" void kernel_launch(void* const* d_in, const int* in_sizes, int n_in,
                              void* d_out, int out_size) {
    const float* C = (const float*)d_in[0];
    float* out = (float*)d_out;

    prep_kernel<<<dim3(N0 / 32, N0 / 32), dim3(32, 8)>>>(C);
    init_kernel<<<1, 256>>>();
    sinkhorn_persistent<<<NBLOCKS, NT>>>();
    final_kernel<<<dim3(NPAD / 4 / 256, NPAD), 256>>>(out);
}

// round 5
// speedup vs baseline: 2.0468x; 1.2792x over previous
#include <cuda_runtime.h>
#include <cuda_bf16.h>
#include <math.h>

#define N0 2048
#define NPAD 4096
#define NBLOCKS 148         // 1 block/SM, all co-resident
#define NT 256              // 8 warps: 7 row-warps (2 rows each) + 1 pad warp
#define NPHASES 100         // 50 iterations x 2 half-steps

// log2(e)/EPS  (EPS = 0.05)
#define KCONST 28.853900817779268f
// 1/4096
#define AMASS 0.000244140625f
#define SCALE 4096.0f

// ---- device state (allocations forbidden; static globals) ----
__device__ float g_y[N0];            // e^{u/eps}
__device__ float g_z[N0];            // e^{v/eps}
__device__ float g_ypad, g_zpad;
__device__ __align__(128) unsigned int g_ctr;    // barrier arrival counter
__device__ __align__(128) unsigned int g_flag;   // barrier release flag (own line)
__device__ float         g_E  [(size_t)N0 * N0];  // exp2(-K*C) fp32 (final pass) 16MB
__device__ __nv_bfloat16 g_Eb [(size_t)N0 * N0];  // bf16 kernel (iterations)      8MB
__device__ __nv_bfloat16 g_Etb[(size_t)N0 * N0];  // bf16 kernel transposed        8MB

__device__ __forceinline__ float ex2(float x) {
    float y; asm("ex2.approx.ftz.f32 %0, %1;" : "=f"(y) : "f"(x)); return y;
}
__device__ __forceinline__ float rcp(float x) {
    float y; asm("rcp.approx.ftz.f32 %0, %1;" : "=f"(y) : "f"(x)); return y;
}
__device__ __forceinline__ float warpRedSum(float v) {
#pragma unroll
    for (int o = 16; o > 0; o >>= 1) v += __shfl_down_sync(0xffffffffu, v, o);
    return v;
}

// ---- prep: E = exp2(-K*C) (fp32), Eb = bf16(E), Etb = bf16(E^T) ----
__global__ void prep_kernel(const float* __restrict__ in) {
    __shared__ float tile[32][33];
    int x = blockIdx.x * 32 + threadIdx.x;
    int y0 = blockIdx.y * 32 + threadIdx.y;
#pragma unroll
    for (int k = 0; k < 32; k += 8) {
        float c = in[(size_t)(y0 + k) * N0 + x];
        float e = ex2(-KCONST * c);
        g_E [(size_t)(y0 + k) * N0 + x] = e;
        g_Eb[(size_t)(y0 + k) * N0 + x] = __float2bfloat16(e);
        tile[threadIdx.y + k][threadIdx.x] = e;
    }
    __syncthreads();
    int x2 = blockIdx.y * 32 + threadIdx.x;
    int y2 = blockIdx.x * 32 + threadIdx.y;
#pragma unroll
    for (int k = 0; k < 32; k += 8)
        g_Etb[(size_t)(y2 + k) * N0 + x2] = __float2bfloat16(tile[threadIdx.x][threadIdx.y + k]);
}

// ---- initial state: v = 0 -> z = 1, z_pad = 1; barrier reset (replay-safe) ----
__global__ void init_kernel() {
    for (int j = threadIdx.x; j < N0; j += blockDim.x) g_z[j] = 1.0f;
    if (threadIdx.x == 0) {
        g_zpad = 1.0f;
        g_ctr = 0u;
        g_flag = 0u;
    }
}

// Persistent kernel, primal (mass) domain, bf16 kernel matrices.
//
// phase even: y_i = AMASS * rcp( sum_j Eb_ij  * z_j + 2048*z_pad )
// phase odd : z_j = AMASS * rcp( sum_i Etb_ji * y_i + 2048*y_pad )
// pad       : x_pad = AMASS * rcp( sum_j in_j + 2048*in_pad )
//
// Per-SM working set: 14 bf16 rows of Eb + 14 of Etb = 114 KB -> stays hot in
// the 228KB L1 across all 100 phases (L1 persists within one launch).
// The input mass vector is staged to smem once per block per phase; y/z/pads
// cross SMs so they use .cg only. bf16 rounding is unbiased and averages out
// over each row-sum; the final pi emission uses the exact fp32 E.
__global__ void __launch_bounds__(NT, 1) sinkhorn_persistent() {
    const int tid = threadIdx.x;
    const int warp = tid >> 5, lane = tid & 31;
    const int b = blockIdx.x;

    const int start = (N0 * b) / NBLOCKS;
    const int cnt = (N0 * (b + 1)) / NBLOCKS - start;    // 13 or 14
    const int r0 = start + 2 * warp;                     // warps 0..6: two rows each
    const bool doR0 = (warp < 7) && (2 * warp < cnt);
    const bool doR1 = (warp < 7) && (2 * warp + 1 < cnt);
    const bool doPad = (b == 0 && warp == 7);

    __shared__ float zs[N0];
    unsigned int phnum = 0;

    for (int ph = 0; ph < NPHASES; ++ph) {
        const int odd = ph & 1;
        const __nv_bfloat16* __restrict__ M = odd ? g_Etb : g_Eb;
        const float* xin = odd ? g_y : g_z;
        float* xout = odd ? g_z : g_y;

        const float xpad_in = __ldcg(odd ? &g_ypad : &g_zpad);
        const float padterm = 2048.0f * xpad_in;

        // stage input masses into smem (256 threads x 2 float4)
        {
            const float4* x4 = (const float4*)xin;
            float4 t0 = __ldcg(x4 + tid);
            float4 t1 = __ldcg(x4 + tid + NT);
            ((float4*)zs)[tid] = t0;
            ((float4*)zs)[tid + NT] = t1;
        }
        __syncthreads();

        const float4* z4 = (const float4*)zs;
        if (warp < 7) {
            // rows r0, r1 (compute both unconditionally — reads are always
            // in-bounds because start+cnt rows of the next block follow;
            // stores are guarded)
            const uint4* e0 = (const uint4*)(M + (size_t)r0 * N0);
            const uint4* e1 = (const uint4*)(M + (size_t)(r0 + 1) * N0);
            float s0 = 0.0f, s1 = 0.0f;
#pragma unroll
            for (int k = 0; k < 8; ++k) {
                const int idx = lane + k * 32;           // uint4 = 8 bf16
                union { uint4 u; __nv_bfloat162 h[4]; } A, B;
                A.u = __ldg(e0 + idx);
                B.u = __ldg(e1 + idx);
                float4 za = z4[2 * idx];
                float4 zb = z4[2 * idx + 1];
                float2 a0 = __bfloat1622float2(A.h[0]);
                float2 a1 = __bfloat1622float2(A.h[1]);
                float2 a2 = __bfloat1622float2(A.h[2]);
                float2 a3 = __bfloat1622float2(A.h[3]);
                s0 = fmaf(a0.x, za.x, s0); s0 = fmaf(a0.y, za.y, s0);
                s0 = fmaf(a1.x, za.z, s0); s0 = fmaf(a1.y, za.w, s0);
                s0 = fmaf(a2.x, zb.x, s0); s0 = fmaf(a2.y, zb.y, s0);
                s0 = fmaf(a3.x, zb.z, s0); s0 = fmaf(a3.y, zb.w, s0);
                float2 b0 = __bfloat1622float2(B.h[0]);
                float2 b1 = __bfloat1622float2(B.h[1]);
                float2 b2 = __bfloat1622float2(B.h[2]);
                float2 b3 = __bfloat1622float2(B.h[3]);
                s1 = fmaf(b0.x, za.x, s1); s1 = fmaf(b0.y, za.y, s1);
                s1 = fmaf(b1.x, za.z, s1); s1 = fmaf(b1.y, za.w, s1);
                s1 = fmaf(b2.x, zb.x, s1); s1 = fmaf(b2.y, zb.y, s1);
                s1 = fmaf(b3.x, zb.z, s1); s1 = fmaf(b3.y, zb.w, s1);
            }
            s0 = warpRedSum(s0);
            s1 = warpRedSum(s1);
            if (lane == 0) {
                if (doR0) __stcg(&xout[r0],     AMASS * rcp(s0 + padterm));
                if (doR1) __stcg(&xout[r0 + 1], AMASS * rcp(s1 + padterm));
            }
        } else if (doPad) {
            float s = 0.0f;
#pragma unroll
            for (int k = 0; k < 16; ++k) {
                float4 z = z4[lane + k * 32];
                s += (z.x + z.y) + (z.z + z.w);
            }
            s = warpRedSum(s);
            if (lane == 0) __stcg(odd ? &g_zpad : &g_ypad, AMASS * rcp(s + padterm));
        }

        // ---- grid barrier: counter + separate release flag, hard spin ----
        ++phnum;
        __syncthreads();                       // all warps done with zs
        if (tid == 0) {
            __threadfence();                   // publish xout/pad writes
            unsigned int t = atomicAdd(&g_ctr, 1u) + 1u;
            if (t == NBLOCKS * phnum) {
                atomicExch(&g_flag, phnum);    // release
            } else {
                while (__ldcg(&g_flag) < phnum) {}
            }
            __threadfence();                   // acquire before next phase reads
        }
        __syncthreads();
    }
}

// ---- out = 4096 * min(1, y_i * z_j * E_ij) over padded 4096x4096 ----
__global__ void __launch_bounds__(256) final_kernel(float* __restrict__ out) {
    int i = blockIdx.y;                                  // 0..4095
    int j4 = blockIdx.x * blockDim.x + threadIdx.x;      // float4 index 0..1023

    float y = (i < N0) ? g_y[i] : g_ypad;

    float4 z4, e4;
    if (j4 < N0 / 4) {
        z4 = ((const float4*)g_z)[j4];
        if (i < N0)
            e4 = ((const float4*)g_E)[(size_t)i * (N0 / 4) + j4];
        else
            e4 = make_float4(1.f, 1.f, 1.f, 1.f);
    } else {
        float zp = g_zpad;
        z4 = make_float4(zp, zp, zp, zp);
        e4 = make_float4(1.f, 1.f, 1.f, 1.f);
    }

    float4 o;
    o.x = SCALE * fminf(1.0f, y * z4.x * e4.x);
    o.y = SCALE * fminf(1.0f, y * z4.y * e4.y);
    o.z = SCALE * fminf(1.0f, y * z4.z * e4.z);
    o.w = SCALE * fminf(1.0f, y * z4.w * e4.w);

    ((float4*)out)[(size_t)i * (NPAD / 4) + j4] = o;
}

extern "C" void kernel_launch(void* const* d_in, const int* in_sizes, int n_in,
                              void* d_out, int out_size) {
    const float* C = (const float*)d_in[0];
    float* out = (float*)d_out;

    prep_kernel<<<dim3(N0 / 32, N0 / 32), dim3(32, 8)>>>(C);
    init_kernel<<<1, 256>>>();
    sinkhorn_persistent<<<NBLOCKS, NT>>>();
    final_kernel<<<dim3(NPAD / 4 / 256, NPAD), 256>>>(out);
}